// round 3
// baseline (speedup 1.0000x reference)
#include <cuda_runtime.h>
#include <cstdint>

#define SS 2048
#define BB 64
#define HH 8
#define KK 12
#define NPOS 11

// Scratch (no allocation allowed in kernel_launch)
__device__ __align__(16) unsigned short g_aq16[SS * HH];
__device__ __align__(16) unsigned short g_ak16[SS * HH];
__device__ __align__(16) unsigned short g_ap16[SS * HH];
__device__ unsigned int g_tbl[HH * 128];            // 8 heads x 4096 bits
__device__ __align__(16) float g_vals[SS * BB];     // values[s][b]

// ---------------------------------------------------------------------------
// Precompute per-(s,h) packed addresses aq/ak/ap (each < 4096, bit-disjoint).
// ---------------------------------------------------------------------------
__global__ void k_addrs(const int* __restrict__ tokens,
                        const int* __restrict__ conn_heads) {
    int s = blockIdx.x;
    __shared__ int tok[BB];
    int t = threadIdx.x;
    tok[t] = tokens[s * BB + t];
    __syncthreads();
    if (t < HH) {
        int aq = 0, ak = 0, ap = 0;
#pragma unroll
        for (int k = 0; k < KK; k++) {
            int c  = conn_heads[t * KK + k];
            int p2 = 1 << (KK - 1 - k);
            if (c < BB)          aq += tok[c] * p2;
            else if (c < 2 * BB) ak += tok[c - BB] * p2;
            else                 ap += ((s >> (NPOS - 1 - (c - 2 * BB))) & 1) * p2;
        }
        g_aq16[s * HH + t] = (unsigned short)aq;
        g_ak16[s * HH + t] = (unsigned short)ak;
        g_ap16[s * HH + t] = (unsigned short)ap;
    }
}

// ---------------------------------------------------------------------------
// Bit-pack head_table (values are exactly 0.0 / 1.0).
// word w covers head h = w>>7, addresses (w&127)*32 .. +31
// ---------------------------------------------------------------------------
__global__ void k_pack(const float* __restrict__ head_table) {
    int w = blockIdx.x * blockDim.x + threadIdx.x;   // 0..1023
    unsigned bits = 0;
#pragma unroll
    for (int b = 0; b < 32; b++)
        bits |= (head_table[w * 32 + b] > 0.5f) ? (1u << b) : 0u;
    g_tbl[w] = bits;
}

// ---------------------------------------------------------------------------
// Precompute values[s][b] = table_v[b, addr_v(s,b)]
// ---------------------------------------------------------------------------
__global__ void k_vals(const int* __restrict__ tokens,
                       const int* __restrict__ conn_v,
                       const float* __restrict__ table_v) {
    int s = blockIdx.x;
    int b = threadIdx.x;
    __shared__ int tok[BB];
    tok[b] = tokens[s * BB + b];
    __syncthreads();
    int addr = 0;
#pragma unroll
    for (int k = 0; k < KK; k++)
        addr += tok[conn_v[b * KK + k]] << (KK - 1 - k);
    g_vals[s * BB + b] = table_v[b * (1 << KK) + addr];
}

// ---------------------------------------------------------------------------
// Main vote kernel: warp per row i, 32 columns per chunk.
//  - packed 16-bit x8 address add (no cross-field carry: sums < 4096)
//  - 8 bit-table lookups from 4KB shared
//  - early exit on vote==8 (max possible; argmax takes first max)
// ---------------------------------------------------------------------------
__global__ void __launch_bounds__(256) k_vote(float* __restrict__ out) {
    __shared__ unsigned tbl[HH * 128];
    int t = threadIdx.x;
#pragma unroll
    for (int w = 0; w < 4; w++) tbl[t + w * 256] = g_tbl[t + w * 256];
    __syncthreads();

    int lane = t & 31;
    int i = (t >> 5) * 256 + blockIdx.x;   // spread rows across blocks for balance

    const uint4* ak4 = (const uint4*)g_ak16;
    const uint4* ap4 = (const uint4*)g_ap16;
    uint4 aq = ((const uint4*)g_aq16)[i];

    int lv = -1, lj = 0;   // per-lane running max (strict >, j ascending -> first)
    int hitJ = -1;

    for (int j0 = 0; j0 <= i; j0 += 32) {
        int j = j0 + lane;
        int vote = -1;
        if (j <= i) {
            uint4 kv = ak4[j];
            uint4 pv = ap4[i - j];
            unsigned s0 = kv.x + pv.x + aq.x;
            unsigned s1 = kv.y + pv.y + aq.y;
            unsigned s2 = kv.z + pv.z + aq.z;
            unsigned s3 = kv.w + pv.w + aq.w;
            unsigned a;
            vote = 0;
            a = s0 & 0xFFFFu; vote += (tbl[      (a >> 5)] >> (a & 31)) & 1;
            a = s0 >> 16;     vote += (tbl[128 + (a >> 5)] >> (a & 31)) & 1;
            a = s1 & 0xFFFFu; vote += (tbl[256 + (a >> 5)] >> (a & 31)) & 1;
            a = s1 >> 16;     vote += (tbl[384 + (a >> 5)] >> (a & 31)) & 1;
            a = s2 & 0xFFFFu; vote += (tbl[512 + (a >> 5)] >> (a & 31)) & 1;
            a = s2 >> 16;     vote += (tbl[640 + (a >> 5)] >> (a & 31)) & 1;
            a = s3 & 0xFFFFu; vote += (tbl[768 + (a >> 5)] >> (a & 31)) & 1;
            a = s3 >> 16;     vote += (tbl[896 + (a >> 5)] >> (a & 31)) & 1;
        }
        unsigned m8 = __ballot_sync(0xffffffffu, vote == HH);
        if (m8) { hitJ = j0 + (__ffs(m8) - 1); break; }   // first max-possible vote wins
        if (vote > lv) { lv = vote; lj = j; }
    }

    int bestV, bestJ;
    if (hitJ >= 0) {
        bestV = HH; bestJ = hitJ;
    } else {
        // warp argmax, tie -> smallest j (first occurrence)
#pragma unroll
        for (int o = 16; o; o >>= 1) {
            int ov = __shfl_xor_sync(0xffffffffu, lv, o);
            int oj = __shfl_xor_sync(0xffffffffu, lj, o);
            if (ov > lv || (ov == lv && oj < lj)) { lv = ov; lj = oj; }
        }
        bestV = lv; bestJ = lj;
    }

    // write 64 floats for row i (out is poisoned -> must write zeros too)
    float4* dst = (float4*)(out + (size_t)i * BB);
    if (lane < 16) {
        if (bestV > 0)
            dst[lane] = ((const float4*)(g_vals + (size_t)bestJ * BB))[lane];
        else
            dst[lane] = make_float4(0.f, 0.f, 0.f, 0.f);
    }
}

// ---------------------------------------------------------------------------
extern "C" void kernel_launch(void* const* d_in, const int* in_sizes, int n_in,
                              void* d_out, int out_size) {
    const int*   tokens     = (const int*)d_in[0];
    const int*   conn_heads = (const int*)d_in[1];
    const float* head_table = (const float*)d_in[2];
    const int*   conn_v     = (const int*)d_in[3];
    const float* table_v    = (const float*)d_in[4];
    float*       out        = (float*)d_out;

    k_addrs<<<SS, BB>>>(tokens, conn_heads);
    k_pack<<<4, 256>>>(head_table);
    k_vals<<<SS, BB>>>(tokens, conn_v, table_v);
    k_vote<<<256, 256>>>(out);
}

// round 5
// speedup vs baseline: 2.0240x; 2.0240x over previous
#include <cuda_runtime.h>
#include <cstdint>

#define SS 2048
#define BB 64
#define HH 8
#define KK 12
#define NPOS 11

// Scratch (no allocation allowed in kernel_launch)
__device__ __align__(16) unsigned short g_aq16[SS * HH];
__device__ __align__(16) unsigned short g_ak16[SS * HH];
__device__ __align__(16) unsigned short g_ap16[SS * HH];
__device__ unsigned int g_tbl[HH * 128];            // 8 heads x 4096 bits
__device__ __align__(16) float g_vals[SS * BB];     // values[s][b]

// ---------------------------------------------------------------------------
// Fused precompute: per-s addrs + per-(s,b) values; first 16 blocks also
// bit-pack head_table (1024 words / 16 blocks / 64 threads = 1 word each).
// ---------------------------------------------------------------------------
__global__ void __launch_bounds__(BB) k_pre(const int* __restrict__ tokens,
                                            const int* __restrict__ conn_heads,
                                            const float* __restrict__ head_table,
                                            const int* __restrict__ conn_v,
                                            const float* __restrict__ table_v) {
    int s = blockIdx.x;
    int t = threadIdx.x;
    __shared__ int tok[BB];
    tok[t] = tokens[s * BB + t];

    if (s < 16) {                       // bit-pack table (values are 0.0/1.0)
        int w = s * BB + t;             // word index 0..1023
        unsigned bits = 0;
#pragma unroll
        for (int b = 0; b < 32; b++)
            bits |= (head_table[w * 32 + b] > 0.5f) ? (1u << b) : 0u;
        g_tbl[w] = bits;
    }
    __syncthreads();

    // values[s][b] = table_v[b, addr_v]
    int addr = 0;
#pragma unroll
    for (int k = 0; k < KK; k++)
        addr += tok[conn_v[t * KK + k]] << (KK - 1 - k);
    g_vals[s * BB + t] = table_v[t * (1 << KK) + addr];

    // per-(s,h) packed addresses aq/ak/ap (each < 4096, bit-disjoint groups)
    if (t < HH) {
        int aq = 0, ak = 0, ap = 0;
#pragma unroll
        for (int k = 0; k < KK; k++) {
            int c  = conn_heads[t * KK + k];
            int p2 = 1 << (KK - 1 - k);
            if (c < BB)          aq += tok[c] * p2;
            else if (c < 2 * BB) ak += tok[c - BB] * p2;
            else                 ap += ((s >> (NPOS - 1 - (c - 2 * BB))) & 1) * p2;
        }
        g_aq16[s * HH + t] = (unsigned short)aq;
        g_ak16[s * HH + t] = (unsigned short)ak;
        g_ap16[s * HH + t] = (unsigned short)ap;
    }
}

// ---------------------------------------------------------------------------
// Vote kernel: BLOCK per row i. 256 threads cover a 256-column chunk.
//  - packed 16-bit x8 address add (no cross-field carry: all sums < 4096)
//  - 8 bit-table lookups from a 4KB shared bitmap
//  - block-wide running argmax via encoded key: (vote<<16) | (2047 - j)
//      max vote wins; tie -> larger (2047-j) -> SMALLER j -> first occurrence,
//      and the running atomicMax across chunks preserves the earliest chunk's
//      entry at equal vote (its key is strictly larger). Matches jnp.argmax.
//  - chunk-level early exit once the running max hits HH (global maximum).
// ---------------------------------------------------------------------------
__global__ void __launch_bounds__(256) k_vote(float* __restrict__ out) {
    __shared__ unsigned tbl[HH * 128];
    __shared__ int s_key;
    int t = threadIdx.x;
    int i = blockIdx.x;
#pragma unroll
    for (int w = 0; w < 4; w++) tbl[t + w * 256] = g_tbl[t + w * 256];
    if (t == 0) s_key = -1;
    __syncthreads();

    const uint4* ak4 = (const uint4*)g_ak16;
    const uint4* ap4 = (const uint4*)g_ap16;
    uint4 aq = ((const uint4*)g_aq16)[i];

    int bk = -1;
    int nch = (i >> 8) + 1;             // ceil((i+1)/256)
    for (int c = 0; c < nch; c++) {
        int j = (c << 8) + t;
        int key = -1;
        if (j <= i) {
            uint4 kv = ak4[j];
            uint4 pv = ap4[i - j];
            unsigned s0 = kv.x + pv.x + aq.x;
            unsigned s1 = kv.y + pv.y + aq.y;
            unsigned s2 = kv.z + pv.z + aq.z;
            unsigned s3 = kv.w + pv.w + aq.w;
            unsigned a;
            int vote = 0;
            a = s0 & 0xFFFFu; vote += (tbl[      (a >> 5)] >> (a & 31)) & 1;
            a = s0 >> 16;     vote += (tbl[128 + (a >> 5)] >> (a & 31)) & 1;
            a = s1 & 0xFFFFu; vote += (tbl[256 + (a >> 5)] >> (a & 31)) & 1;
            a = s1 >> 16;     vote += (tbl[384 + (a >> 5)] >> (a & 31)) & 1;
            a = s2 & 0xFFFFu; vote += (tbl[512 + (a >> 5)] >> (a & 31)) & 1;
            a = s2 >> 16;     vote += (tbl[640 + (a >> 5)] >> (a & 31)) & 1;
            a = s3 & 0xFFFFu; vote += (tbl[768 + (a >> 5)] >> (a & 31)) & 1;
            a = s3 >> 16;     vote += (tbl[896 + (a >> 5)] >> (a & 31)) & 1;
            key = (vote << 16) | (2047 - j);
        }
        // warp-level max, then one atomic per warp into the block running max
#pragma unroll
        for (int o = 16; o; o >>= 1)
            key = max(key, __shfl_xor_sync(0xffffffffu, key, o));
        if ((t & 31) == 0) atomicMax(&s_key, key);
        __syncthreads();
        bk = s_key;
        __syncthreads();                 // all lanes read same bk -> uniform break
        if ((bk >> 16) >= HH) break;     // ceiling vote reached: nothing later wins
    }

    int bv = bk >> 16;
    int bj = 2047 - (bk & 0xFFFF);
    if (t < 16) {                        // 64 floats = 16 x float4
        float4* dst = (float4*)(out + (size_t)i * BB);
        if (bv > 0)
            dst[t] = ((const float4*)(g_vals + (size_t)bj * BB))[t];
        else
            dst[t] = make_float4(0.f, 0.f, 0.f, 0.f);
    }
}

// ---------------------------------------------------------------------------
extern "C" void kernel_launch(void* const* d_in, const int* in_sizes, int n_in,
                              void* d_out, int out_size) {
    const int*   tokens     = (const int*)d_in[0];
    const int*   conn_heads = (const int*)d_in[1];
    const float* head_table = (const float*)d_in[2];
    const int*   conn_v     = (const int*)d_in[3];
    const float* table_v    = (const float*)d_in[4];
    float*       out        = (float*)d_out;

    k_pre<<<SS, BB>>>(tokens, conn_heads, head_table, conn_v, table_v);
    k_vote<<<SS, 256>>>(out);
}

// round 9
// speedup vs baseline: 2.6628x; 1.3156x over previous
#include <cuda_runtime.h>
#include <cstdint>

#define SS 2048
#define BB 64
#define HH 8
#define KK 12
#define NPOS 11

// Scratch (no allocation allowed in kernel_launch)
__device__ __align__(16) unsigned short g_aq16[SS * HH];
__device__ __align__(16) unsigned short g_ak16[SS * HH];
__device__ __align__(16) unsigned short g_ap16[SS * HH];
__device__ unsigned int g_tbl[HH * 128];            // 8 heads x 4096 bits
__device__ __align__(16) float g_vals[SS * BB];     // values[s][b]

// ---------------------------------------------------------------------------
// Fused precompute, 4 rows per 256-thread block (grid 512).
// Blocks 0..3 also bit-pack head_table (4 x 256 = 1024 words).
// ---------------------------------------------------------------------------
__global__ void __launch_bounds__(256) k_pre(const int* __restrict__ tokens,
                                             const int* __restrict__ conn_heads,
                                             const float* __restrict__ head_table,
                                             const int* __restrict__ conn_v,
                                             const float* __restrict__ table_v) {
    int t = threadIdx.x;
    int g = t >> 6;                      // row group 0..3
    int b = t & 63;                      // lane within row
    int s = (blockIdx.x << 2) + g;

    __shared__ int tok[4][BB];
    tok[g][b] = tokens[s * BB + b];

    if (blockIdx.x < 4) {                // bit-pack table (values are 0.0/1.0)
        int w = (blockIdx.x << 8) + t;   // word index 0..1023
        unsigned bits = 0;
#pragma unroll
        for (int k = 0; k < 32; k++)
            bits |= (head_table[w * 32 + k] > 0.5f) ? (1u << k) : 0u;
        g_tbl[w] = bits;
    }
    __syncthreads();

    // values[s][b] = table_v[b, addr_v]
    int addr = 0;
#pragma unroll
    for (int k = 0; k < KK; k++)
        addr += tok[g][conn_v[b * KK + k]] << (KK - 1 - k);
    g_vals[s * BB + b] = table_v[b * (1 << KK) + addr];

    // per-(s,h) packed addresses aq/ak/ap (each < 4096, bit-disjoint groups)
    if (b < HH) {
        int aq = 0, ak = 0, ap = 0;
#pragma unroll
        for (int k = 0; k < KK; k++) {
            int c  = conn_heads[b * KK + k];
            int p2 = 1 << (KK - 1 - k);
            if (c < BB)          aq += tok[g][c] * p2;
            else if (c < 2 * BB) ak += tok[g][c - BB] * p2;
            else                 ap += ((s >> (NPOS - 1 - (c - 2 * BB))) & 1) * p2;
        }
        g_aq16[s * HH + b] = (unsigned short)aq;
        g_ak16[s * HH + b] = (unsigned short)ak;
        g_ap16[s * HH + b] = (unsigned short)ap;
    }
}

// ---------------------------------------------------------------------------
// Vote kernel: block handles rows i = blockIdx and blockIdx + 1024.
// Per 256-col chunk: packed 16-bit x8 address add (no cross-field carry),
// 8 bit-table lookups from a 4KB shared bitmap, per-lane running argmax key
// (vote<<16)|(2047-j) -> max vote, tie -> smallest j (first occurrence, as
// jnp.argmax). Single BAR.RED (__syncthreads_or) per chunk for early exit
// once the ceiling vote HH appears. Full block argmax done ONCE per row.
// ---------------------------------------------------------------------------
__global__ void __launch_bounds__(256) k_vote(float* __restrict__ out) {
    __shared__ unsigned tbl[HH * 128];
    __shared__ int s_red[8];
    int t = threadIdx.x;
#pragma unroll
    for (int w = 0; w < 4; w++) tbl[t + w * 256] = g_tbl[t + w * 256];
    __syncthreads();

    const uint4* ak4 = (const uint4*)g_ak16;
    const uint4* ap4 = (const uint4*)g_ap16;

#pragma unroll
    for (int r = 0; r < 2; r++) {
        int i = blockIdx.x + (r << 10);
        uint4 aq = ((const uint4*)g_aq16)[i];

        int key = -1;                    // per-lane running argmax key
        int nch = (i >> 8) + 1;          // ceil((i+1)/256)
        for (int c = 0; c < nch; c++) {
            int j = (c << 8) + t;
            int hit = 0;
            if (j <= i) {
                uint4 kv = ak4[j];
                uint4 pv = ap4[i - j];
                unsigned s0 = kv.x + pv.x + aq.x;
                unsigned s1 = kv.y + pv.y + aq.y;
                unsigned s2 = kv.z + pv.z + aq.z;
                unsigned s3 = kv.w + pv.w + aq.w;
                unsigned a;
                int vote = 0;
                a = s0 & 0xFFFFu; vote += (tbl[      (a >> 5)] >> (a & 31)) & 1;
                a = s0 >> 16;     vote += (tbl[128 + (a >> 5)] >> (a & 31)) & 1;
                a = s1 & 0xFFFFu; vote += (tbl[256 + (a >> 5)] >> (a & 31)) & 1;
                a = s1 >> 16;     vote += (tbl[384 + (a >> 5)] >> (a & 31)) & 1;
                a = s2 & 0xFFFFu; vote += (tbl[512 + (a >> 5)] >> (a & 31)) & 1;
                a = s2 >> 16;     vote += (tbl[640 + (a >> 5)] >> (a & 31)) & 1;
                a = s3 & 0xFFFFu; vote += (tbl[768 + (a >> 5)] >> (a & 31)) & 1;
                a = s3 >> 16;     vote += (tbl[896 + (a >> 5)] >> (a & 31)) & 1;
                key = max(key, (vote << 16) | (2047 - j));
                hit = (vote == HH);
            }
            if (__syncthreads_or(hit)) break;   // ceiling reached: later j can't win
        }

        // Block argmax, once per row. (The syncthreads_or above, executed at
        // least once, orders the previous row's s_red[0] read vs these writes.)
#pragma unroll
        for (int o = 16; o; o >>= 1)
            key = max(key, __shfl_xor_sync(0xffffffffu, key, o));
        if ((t & 31) == 0) s_red[t >> 5] = key;
        __syncthreads();
        if (t < 32) {
            int k3 = (t < 8) ? s_red[t] : -1;
#pragma unroll
            for (int o = 4; o; o >>= 1)
                k3 = max(k3, __shfl_xor_sync(0xffffffffu, k3, o));
            if (t == 0) s_red[0] = k3;
        }
        __syncthreads();
        int bk = s_red[0];
        int bv = bk >> 16;
        int bj = 2047 - (bk & 0xFFFF);

        if (t < 16) {                    // 64 floats = 16 x float4 (out poisoned)
            float4* dst = (float4*)(out + (size_t)i * BB);
            if (bv > 0)
                dst[t] = ((const float4*)(g_vals + (size_t)bj * BB))[t];
            else
                dst[t] = make_float4(0.f, 0.f, 0.f, 0.f);
        }
    }
}

// ---------------------------------------------------------------------------
extern "C" void kernel_launch(void* const* d_in, const int* in_sizes, int n_in,
                              void* d_out, int out_size) {
    const int*   tokens     = (const int*)d_in[0];
    const int*   conn_heads = (const int*)d_in[1];
    const float* head_table = (const float*)d_in[2];
    const int*   conn_v     = (const int*)d_in[3];
    const float* table_v    = (const float*)d_in[4];
    float*       out        = (float*)d_out;

    k_pre<<<512, 256>>>(tokens, conn_heads, head_table, conn_v, table_v);
    k_vote<<<1024, 256>>>(out);
}

// round 13
// speedup vs baseline: 3.4622x; 1.3002x over previous
#include <cuda_runtime.h>
#include <cstdint>

#define SS 2048
#define BB 64
#define HH 8
#define KK 12
#define NPOS 11

// Scratch (no allocation allowed in kernel_launch)
__device__ __align__(16) unsigned short g_aq16[SS * HH];
__device__ __align__(16) unsigned short g_ak16[SS * HH];
__device__ __align__(16) unsigned short g_ap16[SS * HH];
__device__ __align__(16) unsigned int g_tbl[HH * 128];   // 8 heads x 4096 bits

// ---------------------------------------------------------------------------
// Precompute: per-(s,h) packed addresses (4 rows per block) + table bit-pack
// via one coalesced load + ballot per 32-bit word (spread over 128 blocks).
// ---------------------------------------------------------------------------
__global__ void __launch_bounds__(256) k_pre(const int* __restrict__ tokens,
                                             const int* __restrict__ conn_heads,
                                             const float* __restrict__ head_table) {
    int t = threadIdx.x;

    // bit-pack head_table: word gw packed by one warp (values are 0.0/1.0)
    int gw = (blockIdx.x << 3) + (t >> 5);
    if (gw < HH * 128) {
        unsigned bits = __ballot_sync(0xffffffffu,
                                      head_table[gw * 32 + (t & 31)] > 0.5f);
        if ((t & 31) == 0) g_tbl[gw] = bits;
    }

    int g = t >> 6;                      // row group 0..3
    int b = t & 63;
    int s = (blockIdx.x << 2) + g;
    __shared__ int tok[4][BB];
    tok[g][b] = tokens[s * BB + b];
    __syncthreads();

    if (b < HH) {                        // aq/ak/ap: disjoint bit groups, each <4096
        int aq = 0, ak = 0, ap = 0;
#pragma unroll
        for (int k = 0; k < KK; k++) {
            int c  = conn_heads[b * KK + k];
            int p2 = 1 << (KK - 1 - k);
            if (c < BB)          aq += tok[g][c] * p2;
            else if (c < 2 * BB) ak += tok[g][c - BB] * p2;
            else                 ap += ((s >> (NPOS - 1 - (c - 2 * BB))) & 1) * p2;
        }
        g_aq16[s * HH + b] = (unsigned short)aq;
        g_ak16[s * HH + b] = (unsigned short)ak;
        g_ap16[s * HH + b] = (unsigned short)ap;
    }
}

// ---------------------------------------------------------------------------
// Vote kernel: block handles rows i = blockIdx and blockIdx + 1024.
//  - addr = aq ^ ak ^ ap (disjoint bits -> XOR == ADD, one LOP3 per word,
//    two heads per 32-bit word, no cross-field carry)
//  - 8 bit-table lookups per column from a 4KB shared bitmap
//  - per-lane running argmax key (vote<<16)|(2047-j): max vote, tie -> first j
//  - one __syncthreads_or per 256-col chunk for early exit at ceiling vote HH
//  - values computed ON DEMAND in the epilogue: tokens[bestJ] -> addr_v ->
//    table_v gather (replaces the former full SSxBB g_vals precompute)
//  - PDL: conn_v (pure input) loads before cudaGridDependencySynchronize()
// ---------------------------------------------------------------------------
__global__ void __launch_bounds__(256) k_vote(float* __restrict__ out,
                                              const int* __restrict__ tokens,
                                              const int* __restrict__ conn_v,
                                              const float* __restrict__ table_v) {
    __shared__ unsigned tbl[HH * 128];
    __shared__ int s_cv[BB * KK];        // 768 ints
    __shared__ int s_tok[BB];
    __shared__ int s_red[9];
    int t = threadIdx.x;

    if (t < 192) ((int4*)s_cv)[t] = ((const int4*)conn_v)[t];   // input-only: pre-sync
    cudaGridDependencySynchronize();                             // wait for k_pre
    ((uint4*)tbl)[t] = ((const uint4*)g_tbl)[t];                 // 256 x uint4 = 4KB
    __syncthreads();

    const uint4* ak4 = (const uint4*)g_ak16;
    const uint4* ap4 = (const uint4*)g_ap16;

#pragma unroll
    for (int r = 0; r < 2; r++) {
        int i = blockIdx.x + (r << 10);
        uint4 aq = ((const uint4*)g_aq16)[i];

        int key = -1;
        int nch = (i >> 8) + 1;
        for (int c = 0; c < nch; c++) {
            int j = (c << 8) + t;
            int hit = 0;
            if (j <= i) {
                uint4 kv = ak4[j];
                uint4 pv = ap4[i - j];
                unsigned s0 = kv.x ^ pv.x ^ aq.x;
                unsigned s1 = kv.y ^ pv.y ^ aq.y;
                unsigned s2 = kv.z ^ pv.z ^ aq.z;
                unsigned s3 = kv.w ^ pv.w ^ aq.w;
                int vote = 0;
                vote += (tbl[      ((s0 >>  5) & 127)] >> (s0 & 31)) & 1;
                vote += (tbl[128 + ((s0 >> 21) & 127)] >> ((s0 >> 16) & 31)) & 1;
                vote += (tbl[256 + ((s1 >>  5) & 127)] >> (s1 & 31)) & 1;
                vote += (tbl[384 + ((s1 >> 21) & 127)] >> ((s1 >> 16) & 31)) & 1;
                vote += (tbl[512 + ((s2 >>  5) & 127)] >> (s2 & 31)) & 1;
                vote += (tbl[640 + ((s2 >> 21) & 127)] >> ((s2 >> 16) & 31)) & 1;
                vote += (tbl[768 + ((s3 >>  5) & 127)] >> (s3 & 31)) & 1;
                vote += (tbl[896 + ((s3 >> 21) & 127)] >> ((s3 >> 16) & 31)) & 1;
                key = max(key, (vote << 16) | (2047 - j));
                hit = (vote == HH);
            }
            if (__syncthreads_or(hit)) break;   // ceiling reached: later j can't win
        }

        // block argmax, once per row
#pragma unroll
        for (int o = 16; o; o >>= 1)
            key = max(key, __shfl_xor_sync(0xffffffffu, key, o));
        if ((t & 31) == 0) s_red[t >> 5] = key;
        __syncthreads();
        if (t < 32) {
            int k3 = (t < 8) ? s_red[t] : -1;
#pragma unroll
            for (int o = 4; o; o >>= 1)
                k3 = max(k3, __shfl_xor_sync(0xffffffffu, k3, o));
            if (t == 0) s_red[8] = k3;
        }
        __syncthreads();
        int bk = s_red[8];
        int bv = bk >> 16;
        int bj = 2047 - (bk & 0xFFFF);

        // on-demand values: out[i] = table_v[b, addr_v(bestJ, b)] or 0
        if (bv > 0 && t < BB) s_tok[t] = tokens[bj * BB + t];
        __syncthreads();
        if (t < BB) {
            float v = 0.f;
            if (bv > 0) {
                int addr = 0;
#pragma unroll
                for (int k = 0; k < KK; k++)
                    addr += s_tok[s_cv[t * KK + k]] << (KK - 1 - k);
                v = table_v[t * (1 << KK) + addr];
            }
            out[(size_t)i * BB + t] = v;
        }
    }
}

// ---------------------------------------------------------------------------
extern "C" void kernel_launch(void* const* d_in, const int* in_sizes, int n_in,
                              void* d_out, int out_size) {
    const int*   tokens     = (const int*)d_in[0];
    const int*   conn_heads = (const int*)d_in[1];
    const float* head_table = (const float*)d_in[2];
    const int*   conn_v     = (const int*)d_in[3];
    const float* table_v    = (const float*)d_in[4];
    float*       out        = (float*)d_out;

    k_pre<<<512, 256>>>(tokens, conn_heads, head_table);

    // PDL: let k_vote launch early and run its input-only prologue while
    // k_pre drains; cudaGridDependencySynchronize() guards the g_* reads.
    cudaLaunchConfig_t cfg = {};
    cfg.gridDim  = dim3(1024);
    cfg.blockDim = dim3(256);
    cfg.stream   = 0;
    cudaLaunchAttribute attr[1];
    attr[0].id = cudaLaunchAttributeProgrammaticStreamSerialization;
    attr[0].val.programmaticStreamSerializationAllowed = 1;
    cfg.attrs = attr;
    cfg.numAttrs = 1;
    cudaLaunchKernelEx(&cfg, k_vote, out, tokens, conn_v, table_v);
}